// round 7
// baseline (speedup 1.0000x reference)
#include <cuda_runtime.h>
#include <cuda_bf16.h>
#include <cstdint>

// NF4 codebook (float32, matches bitsandbytes / reference exactly)
static __device__ __constant__ float NF4_TBL[16] = {
    -1.0f, -0.6961928009986877f, -0.5250730514526367f, -0.39491748809814453f,
    -0.28444138169288635f, -0.18477343022823334f, -0.09105003625154495f, 0.0f,
    0.07958029955625534f, 0.16093020141124725f, 0.24611230194568634f,
    0.33791524171829224f, 0.4407098591327667f, 0.5626170039176941f,
    0.7229568362236023f, 1.0f
};

#define REPS  8     // lane&7 replication -> conflict-free LDS.128
#define NROWS 128   // power of two; rows 65..127 are (never-accessed) padding

static __device__ __forceinline__ float warp_absmax(float v) {
#pragma unroll
    for (int s = 16; s > 0; s >>= 1)
        v = fmaxf(v, __shfl_xor_sync(0xffffffffu, v, s));
    return v;
}

static __device__ __forceinline__ uint32_t smem_u32(const void* p) {
    uint32_t a;
    asm("{ .reg .u64 t; cvta.to.shared.u64 t, %1; cvt.u32.u64 %0, t; }"
        : "=r"(a) : "l"(p));
    return a;
}

__global__ void __launch_bounds__(256, 5)
nf4_qdq_kernel(const float* __restrict__ x, float* __restrict__ out, int nblk) {
    __shared__ float4 lut[NROWS * REPS];   // entry i at lut[i*8 + rep]

    // ---- build LUT: ONE thread per entry (the 15-step scan runs 65x/CTA,
    // not 256x) -- this was ~70% of all issued instructions before ----
    {
        int i = threadIdx.x;
        if (i < NROWS) {
            float4 e = make_float4(0.f, 0.f, 0.f, 0.f);
            if (i < 65) {
                float loEdge = (float)i - 0.5f;   // bucket i covers t in [i-.5, i+.5)
                float hiEdge = (float)i + 0.5f;
                int lo = 0, hi = 0;
#pragma unroll
                for (int j = 0; j < 15; j++) {
                    float mt = fmaf((NF4_TBL[j] + NF4_TBL[j + 1]) * 0.5f, 32.0f, 32.0f);
                    lo += (mt < loEdge);
                    hi += (mt < hiEdge);
                }
                float bnd = 3.0e38f;
                if (hi > lo)  // at most one midpoint per bucket (min gap 2.73 > 1.0)
                    bnd = fmaf((NF4_TBL[lo] + NF4_TBL[lo + 1]) * 0.5f, 32.0f, 32.0f);
                e.x = bnd;
                e.y = NF4_TBL[lo];
                e.z = NF4_TBL[hi];
            }
#pragma unroll
            for (int r = 0; r < REPS; r++)
                lut[i * REPS + r] = e;
        }
    }
    __syncthreads();

    // ---- one warp per NF4 block of 512 floats (= 128 float4) ----
    int gw = blockIdx.x * 8 + (threadIdx.x >> 5);
    if (gw >= nblk) return;
    int lane = threadIdx.x & 31;

    const float4* __restrict__ xi = reinterpret_cast<const float4*>(x) + (size_t)gw * 128 + lane;
    float4* __restrict__       xo = reinterpret_cast<float4*>(out)     + (size_t)gw * 128 + lane;

    float4 a = __ldcs(xi + 0);
    float4 b = __ldcs(xi + 32);
    float4 c = __ldcs(xi + 64);
    float4 d = __ldcs(xi + 96);

    // ---- block absmax (registers + shfl only) ----
    float am = fabsf(a.x);
    am = fmaxf(am, fabsf(a.y)); am = fmaxf(am, fabsf(a.z)); am = fmaxf(am, fabsf(a.w));
    am = fmaxf(am, fabsf(b.x)); am = fmaxf(am, fabsf(b.y)); am = fmaxf(am, fabsf(b.z)); am = fmaxf(am, fabsf(b.w));
    am = fmaxf(am, fabsf(c.x)); am = fmaxf(am, fabsf(c.y)); am = fmaxf(am, fabsf(c.z)); am = fmaxf(am, fabsf(c.w));
    am = fmaxf(am, fabsf(d.x)); am = fmaxf(am, fabsf(d.y)); am = fmaxf(am, fabsf(d.z)); am = fmaxf(am, fabsf(d.w));
    am = warp_absmax(am);

    float s2 = (am > 0.0f) ? (32.0f / am) : 0.0f;

    // m = t + 2^23 has bits 0x4B000000 + bucket (bucket in [0,64], since |x|<=am
    // => t in [0,64+eps]).  (bits << 7) mod 2^32 = bucket*128 + 0x80000000, so
    // pre-biasing the smem base by +0x80000000 makes the address one LEA.
    uint32_t base_off = smem_u32(lut) + (uint32_t)(lane & 7) * 16u + 0x80000000u;

    auto q = [&](float xv) -> float {
        float t = fmaf(xv, s2, 32.0f);
        float m = t + 8388608.0f;
        uint32_t off = base_off + (((uint32_t)__float_as_int(m)) << 7);
        float ex, ey, ez, ew;
        asm("ld.shared.v4.f32 {%0,%1,%2,%3}, [%4];"
            : "=f"(ex), "=f"(ey), "=f"(ez), "=f"(ew) : "r"(off));
        float v = (t > ex) ? ez : ey;        // resolve the one boundary
        return v * am;                        // exact NF4[idx] * absmax
    };

    a.x = q(a.x); a.y = q(a.y); a.z = q(a.z); a.w = q(a.w);
    b.x = q(b.x); b.y = q(b.y); b.z = q(b.z); b.w = q(b.w);
    c.x = q(c.x); c.y = q(c.y); c.z = q(c.z); c.w = q(c.w);
    d.x = q(d.x); d.y = q(d.y); d.z = q(d.z); d.w = q(d.w);

    __stcs(xo + 0,  a);
    __stcs(xo + 32, b);
    __stcs(xo + 64, c);
    __stcs(xo + 96, d);
}

extern "C" void kernel_launch(void* const* d_in, const int* in_sizes, int n_in,
                              void* d_out, int out_size) {
    const float* x = (const float*)d_in[0];
    float* out = (float*)d_out;
    int n = in_sizes[0];
    int nblk = n / 512;                 // reference requires n % 512 == 0
    int ctas = (nblk + 7) / 8;          // 8 warps (= 8 NF4 blocks) per CTA
    nf4_qdq_kernel<<<ctas, 256>>>(x, out, nblk);
}

// round 8
// speedup vs baseline: 1.0189x; 1.0189x over previous
#include <cuda_runtime.h>
#include <cuda_bf16.h>
#include <cstdint>

// NF4 codebook (float32, matches bitsandbytes / reference exactly)
static __device__ __constant__ float NF4_TBL[16] = {
    -1.0f, -0.6961928009986877f, -0.5250730514526367f, -0.39491748809814453f,
    -0.28444138169288635f, -0.18477343022823334f, -0.09105003625154495f, 0.0f,
    0.07958029955625534f, 0.16093020141124725f, 0.24611230194568634f,
    0.33791524171829224f, 0.4407098591327667f, 0.5626170039176941f,
    0.7229568362236023f, 1.0f
};

#define REPS  8     // lane&7 replication -> conflict-free LDS.128
#define NROWS 128   // power of two so (bits & 127) is always a valid row

static __device__ __forceinline__ float warp_absmax(float v) {
#pragma unroll
    for (int s = 16; s > 0; s >>= 1)
        v = fmaxf(v, __shfl_xor_sync(0xffffffffu, v, s));
    return v;
}

__global__ void __launch_bounds__(256, 5)
nf4_qdq_kernel(const float* __restrict__ x, float* __restrict__ out, int nblk) {
    __shared__ float4 lut[NROWS * REPS];   // entry i at lut[i*8 + rep]

    // ---- build LUT: ONE thread per entry (15-step scan runs 65x per CTA,
    // not 256x). Bucket i covers t in [i-0.5, i+0.5); each bucket contains
    // at most one decision midpoint (min midpoint gap 2.73 t-units > 1.0). ----
    {
        int i = threadIdx.x;
        if (i < NROWS) {
            float4 e = make_float4(0.f, 0.f, 0.f, 0.f);
            if (i < 65) {
                float loEdge = (float)i - 0.5f;
                float hiEdge = (float)i + 0.5f;
                int lo = 0, hi = 0;
#pragma unroll
                for (int j = 0; j < 15; j++) {
                    float mt = fmaf((NF4_TBL[j] + NF4_TBL[j + 1]) * 0.5f, 32.0f, 32.0f);
                    lo += (mt < loEdge);
                    hi += (mt < hiEdge);
                }
                float bnd = 3.0e38f;
                if (hi > lo)
                    bnd = fmaf((NF4_TBL[lo] + NF4_TBL[lo + 1]) * 0.5f, 32.0f, 32.0f);
                e.x = bnd;
                e.y = NF4_TBL[lo];
                e.z = NF4_TBL[hi];
            }
#pragma unroll
            for (int r = 0; r < REPS; r++)
                lut[i * REPS + r] = e;
        }
    }
    __syncthreads();

    // ---- one warp per NF4 block of 512 floats (= 128 float4) ----
    int gw = blockIdx.x * 8 + (threadIdx.x >> 5);
    if (gw >= nblk) return;
    int lane = threadIdx.x & 31;

    const float4* __restrict__ xi = reinterpret_cast<const float4*>(x) + (size_t)gw * 128 + lane;
    float4* __restrict__       xo = reinterpret_cast<float4*>(out)     + (size_t)gw * 128 + lane;

    float4 a = __ldcs(xi + 0);
    float4 b = __ldcs(xi + 32);
    float4 c = __ldcs(xi + 64);
    float4 d = __ldcs(xi + 96);

    // ---- block absmax (registers + shfl only) ----
    float am = fabsf(a.x);
    am = fmaxf(am, fabsf(a.y)); am = fmaxf(am, fabsf(a.z)); am = fmaxf(am, fabsf(a.w));
    am = fmaxf(am, fabsf(b.x)); am = fmaxf(am, fabsf(b.y)); am = fmaxf(am, fabsf(b.z)); am = fmaxf(am, fabsf(b.w));
    am = fmaxf(am, fabsf(c.x)); am = fmaxf(am, fabsf(c.y)); am = fmaxf(am, fabsf(c.z)); am = fmaxf(am, fabsf(c.w));
    am = fmaxf(am, fabsf(d.x)); am = fmaxf(am, fabsf(d.y)); am = fmaxf(am, fabsf(d.z)); am = fmaxf(am, fabsf(d.w));
    am = warp_absmax(am);

    float s2 = (am > 0.0f) ? (32.0f / am) : 0.0f;

    const float4* __restrict__ lutl = lut + (lane & 7);

    // |x| <= am  =>  t in [0, 64+eps]; m = t + 2^23 has bits 0x4B000000 + bi
    // with bi in [0,64], so (bits & 127) IS the bucket index. Plain LOP3+IMAD
    // addressing -- shared addresses stay in [0,16KB) (high-bit-set shared
    // addresses take an L1TEX slow path on sm_100; see R6 regression).
    auto q = [&](float xv) -> float {
        float t = fmaf(xv, s2, 32.0f);
        float m = t + 8388608.0f;
        unsigned bi = ((unsigned)__float_as_int(m)) & 127u;
        float4 e = lutl[bi * REPS];          // conflict-free LDS.128
        float v = (t > e.x) ? e.z : e.y;     // resolve the one boundary
        return v * am;                       // exact NF4[idx] * absmax
    };

    a.x = q(a.x); a.y = q(a.y); a.z = q(a.z); a.w = q(a.w);
    b.x = q(b.x); b.y = q(b.y); b.z = q(b.z); b.w = q(b.w);
    c.x = q(c.x); c.y = q(c.y); c.z = q(c.z); c.w = q(c.w);
    d.x = q(d.x); d.y = q(d.y); d.z = q(d.z); d.w = q(d.w);

    __stcs(xo + 0,  a);
    __stcs(xo + 32, b);
    __stcs(xo + 64, c);
    __stcs(xo + 96, d);
}

extern "C" void kernel_launch(void* const* d_in, const int* in_sizes, int n_in,
                              void* d_out, int out_size) {
    const float* x = (const float*)d_in[0];
    float* out = (float*)d_out;
    int n = in_sizes[0];
    int nblk = n / 512;                 // reference requires n % 512 == 0
    int ctas = (nblk + 7) / 8;          // 8 warps (= 8 NF4 blocks) per CTA
    nf4_qdq_kernel<<<ctas, 256>>>(x, out, nblk);
}

// round 9
// speedup vs baseline: 1.3325x; 1.3077x over previous
#include <cuda_runtime.h>
#include <cuda_bf16.h>
#include <cstdint>

// NF4 codebook (float32, matches bitsandbytes / reference exactly)
static __device__ __constant__ float NF4_TBL[16] = {
    -1.0f, -0.6961928009986877f, -0.5250730514526367f, -0.39491748809814453f,
    -0.28444138169288635f, -0.18477343022823334f, -0.09105003625154495f, 0.0f,
    0.07958029955625534f, 0.16093020141124725f, 0.24611230194568634f,
    0.33791524171829224f, 0.4407098591327667f, 0.5626170039176941f,
    0.7229568362236023f, 1.0f
};

#define REPS  8     // lane&7 replication -> conflict-free LDS.128 in main loop
#define NROWS 128   // power of two so (bits & 127) is always a valid row

static __device__ __forceinline__ float warp_absmax(float v) {
#pragma unroll
    for (int s = 16; s > 0; s >>= 1)
        v = fmaxf(v, __shfl_xor_sync(0xffffffffu, v, s));
    return v;
}

__global__ void __launch_bounds__(256, 5)
nf4_qdq_kernel(const float* __restrict__ x, float* __restrict__ out, int nblk) {
    __shared__ float4 lut[NROWS * REPS];   // entry i at lut[i*8 + rep]
    __shared__ float4 entry[NROWS];        // staging: one copy per bucket

    // ---- phase 1: thread i computes entry i (15-step scan runs 128x/CTA).
    // STS pattern: consecutive lanes -> consecutive float4s -> conflict-free.
    {
        int i = threadIdx.x;
        if (i < NROWS) {
            float4 e = make_float4(0.f, 0.f, 0.f, 0.f);
            if (i < 65) {
                float loEdge = (float)i - 0.5f;   // bucket i covers t in [i-.5, i+.5)
                float hiEdge = (float)i + 0.5f;
                int lo = 0, hi = 0;
#pragma unroll
                for (int j = 0; j < 15; j++) {
                    float mt = fmaf((NF4_TBL[j] + NF4_TBL[j + 1]) * 0.5f, 32.0f, 32.0f);
                    lo += (mt < loEdge);
                    hi += (mt < hiEdge);
                }
                float bnd = 3.0e38f;
                if (hi > lo)  // at most one midpoint per bucket (min gap 2.73 > 1.0)
                    bnd = fmaf((NF4_TBL[lo] + NF4_TBL[lo + 1]) * 0.5f, 32.0f, 32.0f);
                e.x = bnd;
                e.y = NF4_TBL[lo];
                e.z = NF4_TBL[hi];
            }
            entry[i] = e;
        }
    }
    __syncthreads();

    // ---- phase 2: replicate 8x. Reads: 8-lane broadcast of 4 distinct lines
    // (conflict-free). Writes: consecutive lanes -> consecutive float4s
    // (conflict-free). NO warp ever stores a same-bank-group column pattern --
    // that pattern (thread i writing lut[i*8..i*8+7]) was a 32-way STS
    // conflict burning ~30us of L1 in the previous two rounds.
    for (int d = threadIdx.x; d < NROWS * REPS; d += 256)
        lut[d] = entry[d >> 3];
    __syncthreads();

    // ---- one warp per NF4 block of 512 floats (= 128 float4) ----
    int gw = blockIdx.x * 8 + (threadIdx.x >> 5);
    if (gw >= nblk) return;
    int lane = threadIdx.x & 31;

    const float4* __restrict__ xi = reinterpret_cast<const float4*>(x) + (size_t)gw * 128 + lane;
    float4* __restrict__       xo = reinterpret_cast<float4*>(out)     + (size_t)gw * 128 + lane;

    float4 a = __ldcs(xi + 0);
    float4 b = __ldcs(xi + 32);
    float4 c = __ldcs(xi + 64);
    float4 d = __ldcs(xi + 96);

    // ---- block absmax (registers + shfl only) ----
    float am = fabsf(a.x);
    am = fmaxf(am, fabsf(a.y)); am = fmaxf(am, fabsf(a.z)); am = fmaxf(am, fabsf(a.w));
    am = fmaxf(am, fabsf(b.x)); am = fmaxf(am, fabsf(b.y)); am = fmaxf(am, fabsf(b.z)); am = fmaxf(am, fabsf(b.w));
    am = fmaxf(am, fabsf(c.x)); am = fmaxf(am, fabsf(c.y)); am = fmaxf(am, fabsf(c.z)); am = fmaxf(am, fabsf(c.w));
    am = fmaxf(am, fabsf(d.x)); am = fmaxf(am, fabsf(d.y)); am = fmaxf(am, fabsf(d.z)); am = fmaxf(am, fabsf(d.w));
    am = warp_absmax(am);

    float s2 = (am > 0.0f) ? (32.0f / am) : 0.0f;

    const float4* __restrict__ lutl = lut + (lane & 7);

    // |x| <= am  =>  t in [0, 64+eps]; m = t + 2^23 has bits 0x4B000000 + bi
    // with bi in [0,64], so (bits & 127) IS the bucket index.
    auto q = [&](float xv) -> float {
        float t = fmaf(xv, s2, 32.0f);
        float m = t + 8388608.0f;
        unsigned bi = ((unsigned)__float_as_int(m)) & 127u;
        float4 e = lutl[bi * REPS];          // conflict-free LDS.128
        float v = (t > e.x) ? e.z : e.y;     // resolve the one boundary
        return v * am;                       // exact NF4[idx] * absmax
    };

    a.x = q(a.x); a.y = q(a.y); a.z = q(a.z); a.w = q(a.w);
    b.x = q(b.x); b.y = q(b.y); b.z = q(b.z); b.w = q(b.w);
    c.x = q(c.x); c.y = q(c.y); c.z = q(c.z); c.w = q(c.w);
    d.x = q(d.x); d.y = q(d.y); d.z = q(d.z); d.w = q(d.w);

    __stcs(xo + 0,  a);
    __stcs(xo + 32, b);
    __stcs(xo + 64, c);
    __stcs(xo + 96, d);
}

extern "C" void kernel_launch(void* const* d_in, const int* in_sizes, int n_in,
                              void* d_out, int out_size) {
    const float* x = (const float*)d_in[0];
    float* out = (float*)d_out;
    int n = in_sizes[0];
    int nblk = n / 512;                 // reference requires n % 512 == 0
    int ctas = (nblk + 7) / 8;          // 8 warps (= 8 NF4 blocks) per CTA
    nf4_qdq_kernel<<<ctas, 256>>>(x, out, nblk);
}

// round 12
// speedup vs baseline: 1.3913x; 1.0442x over previous
#include <cuda_runtime.h>
#include <cuda_fp16.h>
#include <cuda_bf16.h>
#include <cstdint>

// NF4 codebook (float32, matches bitsandbytes / reference exactly)
static __device__ __constant__ float NF4_TBL[16] = {
    -1.0f, -0.6961928009986877f, -0.5250730514526367f, -0.39491748809814453f,
    -0.28444138169288635f, -0.18477343022823334f, -0.09105003625154495f, 0.0f,
    0.07958029955625534f, 0.16093020141124725f, 0.24611230194568634f,
    0.33791524171829224f, 0.4407098591327667f, 0.5626170039176941f,
    0.7229568362236023f, 1.0f
};

#define REPS  16    // lane&15 replication -> conflict-free LDS.64 (row = 128B)
#define NROWS 128   // power of two so (bits & 127) is always a valid row

static __device__ __forceinline__ float warp_absmax(float v) {
#pragma unroll
    for (int s = 16; s > 0; s >>= 1)
        v = fmaxf(v, __shfl_xor_sync(0xffffffffu, v, s));
    return v;
}

__global__ void __launch_bounds__(256, 5)
nf4_qdq_kernel(const float* __restrict__ x, float* __restrict__ out, int nblk) {
    // entry: low 32 bits = fp32 boundary_t (exact compare),
    //        high 32 bits = packed half2 {lo, hi} codebook values
    __shared__ unsigned long long lut[NROWS * REPS];   // 16 KB
    __shared__ unsigned long long entry[NROWS];        // staging

    // ---- phase 1: thread i computes entry i (conflict-free STS) ----
    {
        int i = threadIdx.x;
        if (i < NROWS) {
            unsigned long long raw = 0ull;
            if (i < 65) {
                float loEdge = (float)i - 0.5f;   // bucket i covers t in [i-.5, i+.5)
                float hiEdge = (float)i + 0.5f;
                int lo = 0, hi = 0;
#pragma unroll
                for (int j = 0; j < 15; j++) {
                    float mt = fmaf((NF4_TBL[j] + NF4_TBL[j + 1]) * 0.5f, 32.0f, 32.0f);
                    lo += (mt < loEdge);
                    hi += (mt < hiEdge);
                }
                float bnd = 3.0e38f;
                if (hi > lo)  // at most one midpoint per bucket (min gap 2.73 > 1.0)
                    bnd = fmaf((NF4_TBL[lo] + NF4_TBL[lo + 1]) * 0.5f, 32.0f, 32.0f);
                unsigned lo16 = __half_as_ushort(__float2half_rn(NF4_TBL[lo]));
                unsigned hi16 = __half_as_ushort(__float2half_rn(NF4_TBL[hi]));
                raw = ((unsigned long long)((hi16 << 16) | lo16) << 32)
                    | (unsigned)__float_as_int(bnd);
            }
            entry[i] = raw;
        }
    }
    __syncthreads();

    // ---- phase 2: replicate 16x (broadcast reads, consecutive-lane writes;
    // both conflict-free -- see R8: column-pattern STS was a 32-way conflict) ----
    for (int d = threadIdx.x; d < NROWS * REPS; d += 256)
        lut[d] = entry[d >> 4];
    __syncthreads();

    // ---- one warp per NF4 block of 512 floats (= 128 float4) ----
    int gw = blockIdx.x * 8 + (threadIdx.x >> 5);
    if (gw >= nblk) return;
    int lane = threadIdx.x & 31;

    const float4* __restrict__ xi = reinterpret_cast<const float4*>(x) + (size_t)gw * 128 + lane;
    float4* __restrict__       xo = reinterpret_cast<float4*>(out)     + (size_t)gw * 128 + lane;

    float4 a = __ldcs(xi + 0);
    float4 b = __ldcs(xi + 32);
    float4 c = __ldcs(xi + 64);
    float4 d = __ldcs(xi + 96);

    // ---- block absmax (registers + shfl only) ----
    float am = fabsf(a.x);
    am = fmaxf(am, fabsf(a.y)); am = fmaxf(am, fabsf(a.z)); am = fmaxf(am, fabsf(a.w));
    am = fmaxf(am, fabsf(b.x)); am = fmaxf(am, fabsf(b.y)); am = fmaxf(am, fabsf(b.z)); am = fmaxf(am, fabsf(b.w));
    am = fmaxf(am, fabsf(c.x)); am = fmaxf(am, fabsf(c.y)); am = fmaxf(am, fabsf(c.z)); am = fmaxf(am, fabsf(c.w));
    am = fmaxf(am, fabsf(d.x)); am = fmaxf(am, fabsf(d.y)); am = fmaxf(am, fabsf(d.z)); am = fmaxf(am, fabsf(d.w));
    am = warp_absmax(am);

    float s2 = (am > 0.0f) ? (32.0f / am) : 0.0f;

    const unsigned long long* __restrict__ lutl = lut + (lane & 15);

    // |x| <= am  =>  t in [0, 64+eps]; m = t + 2^23 has bits 0x4B000000 + bi
    // with bi in [0,64], so (bits & 127) IS the bucket index. LDS.64 per
    // element: half-warp phase covers 16 lanes x 8B = 128B, banks {2k,2k+1}
    // distinct per lane -> conflict-free for arbitrary per-lane buckets.
    auto q = [&](float xv) -> float {
        float t = fmaf(xv, s2, 32.0f);
        float m = t + 8388608.0f;
        unsigned bi = ((unsigned)__float_as_int(m)) & 127u;
        unsigned long long raw = lutl[bi * REPS];
        float bnd = __uint_as_float((unsigned)raw);
        unsigned codes = (unsigned)(raw >> 32);
        unsigned s = codes >> ((t > bnd) ? 16 : 0);   // pick hi or lo half
        float v = __half2float(__ushort_as_half((unsigned short)s));
        return v * am;                                 // NF4[idx] (fp16) * absmax
    };

    a.x = q(a.x); a.y = q(a.y); a.z = q(a.z); a.w = q(a.w);
    b.x = q(b.x); b.y = q(b.y); b.z = q(b.z); b.w = q(b.w);
    c.x = q(c.x); c.y = q(c.y); c.z = q(c.z); c.w = q(c.w);
    d.x = q(d.x); d.y = q(d.y); d.z = q(d.z); d.w = q(d.w);

    __stcs(xo + 0,  a);
    __stcs(xo + 32, b);
    __stcs(xo + 64, c);
    __stcs(xo + 96, d);
}

extern "C" void kernel_launch(void* const* d_in, const int* in_sizes, int n_in,
                              void* d_out, int out_size) {
    const float* x = (const float*)d_in[0];
    float* out = (float*)d_out;
    int n = in_sizes[0];
    int nblk = n / 512;                 // reference requires n % 512 == 0
    int ctas = (nblk + 7) / 8;          // 8 warps (= 8 NF4 blocks) per CTA
    nf4_qdq_kernel<<<ctas, 256>>>(x, out, nblk);
}

// round 14
// speedup vs baseline: 1.4382x; 1.0337x over previous
#include <cuda_runtime.h>
#include <cuda_fp16.h>
#include <cuda_bf16.h>
#include <cstdint>

// NF4 codebook (float32, matches bitsandbytes / reference exactly)
static __device__ __constant__ float NF4_TBL[16] = {
    -1.0f, -0.6961928009986877f, -0.5250730514526367f, -0.39491748809814453f,
    -0.28444138169288635f, -0.18477343022823334f, -0.09105003625154495f, 0.0f,
    0.07958029955625534f, 0.16093020141124725f, 0.24611230194568634f,
    0.33791524171829224f, 0.4407098591327667f, 0.5626170039176941f,
    0.7229568362236023f, 1.0f
};

#define REPS  16    // lane&15 replication -> conflict-free LDS.64 (row = 128B)
#define NROWS 128   // power of two so (bits & 127) is always a valid row

static __device__ __forceinline__ float red4(const float4& v) {
    return fmaxf(fmaxf(fabsf(v.x), fabsf(v.y)), fmaxf(fabsf(v.z), fabsf(v.w)));
}

__global__ void __launch_bounds__(256, 4)
nf4_qdq_kernel(const float* __restrict__ x, float* __restrict__ out, int nblk) {
    // entry: low 32 bits = fp32 boundary_t (exact compare),
    //        high 32 bits = packed half2 {lo, hi} codebook values
    __shared__ unsigned long long lut[NROWS * REPS];   // 16 KB
    __shared__ unsigned long long entry[NROWS];        // staging

    // ---- phase 1: thread i computes entry i (conflict-free STS) ----
    {
        int i = threadIdx.x;
        if (i < NROWS) {
            unsigned long long raw = 0ull;
            if (i < 65) {
                float loEdge = (float)i - 0.5f;   // bucket i covers t in [i-.5, i+.5)
                float hiEdge = (float)i + 0.5f;
                int lo = 0, hi = 0;
#pragma unroll
                for (int j = 0; j < 15; j++) {
                    float mt = fmaf((NF4_TBL[j] + NF4_TBL[j + 1]) * 0.5f, 32.0f, 32.0f);
                    lo += (mt < loEdge);
                    hi += (mt < hiEdge);
                }
                float bnd = 3.0e38f;
                if (hi > lo)  // at most one midpoint per bucket (min gap 2.73 > 1.0)
                    bnd = fmaf((NF4_TBL[lo] + NF4_TBL[lo + 1]) * 0.5f, 32.0f, 32.0f);
                unsigned lo16 = __half_as_ushort(__float2half_rn(NF4_TBL[lo]));
                unsigned hi16 = __half_as_ushort(__float2half_rn(NF4_TBL[hi]));
                raw = ((unsigned long long)((hi16 << 16) | lo16) << 32)
                    | (unsigned)__float_as_int(bnd);
            }
            entry[i] = raw;
        }
    }
    __syncthreads();

    // ---- phase 2: replicate 16x (broadcast reads, consecutive-lane writes;
    // both conflict-free -- R8 lesson: column-pattern STS = 32-way conflict) ----
    for (int d = threadIdx.x; d < NROWS * REPS; d += 256)
        lut[d] = entry[d >> 4];
    __syncthreads();

    // ---- TWO NF4 blocks (1024 floats) per warp: batch all 8 LDG.128s first
    // (MLP 8/thread), overlap the two shfl-reduce chains, then process both.
    int gw = blockIdx.x * 8 + (threadIdx.x >> 5);   // pair index
    int blk0 = gw * 2;
    if (blk0 >= nblk) return;
    int blk1 = blk0 + 1;
    bool has1 = (blk1 < nblk);
    int lane = threadIdx.x & 31;

    const float4* __restrict__ xi0 = reinterpret_cast<const float4*>(x) + (size_t)blk0 * 128 + lane;
    const float4* __restrict__ xi1 = reinterpret_cast<const float4*>(x) + (size_t)(has1 ? blk1 : blk0) * 128 + lane;
    float4* __restrict__ xo0 = reinterpret_cast<float4*>(out) + (size_t)blk0 * 128 + lane;
    float4* __restrict__ xo1 = reinterpret_cast<float4*>(out) + (size_t)blk1 * 128 + lane;

    float4 a0 = __ldcs(xi0 + 0);
    float4 b0 = __ldcs(xi0 + 32);
    float4 c0 = __ldcs(xi0 + 64);
    float4 d0 = __ldcs(xi0 + 96);
    float4 a1 = __ldcs(xi1 + 0);
    float4 b1 = __ldcs(xi1 + 32);
    float4 c1 = __ldcs(xi1 + 64);
    float4 d1 = __ldcs(xi1 + 96);

    // ---- both block absmaxes; the two 5-step shfl chains interleave ----
    float am0 = fmaxf(fmaxf(red4(a0), red4(b0)), fmaxf(red4(c0), red4(d0)));
    float am1 = fmaxf(fmaxf(red4(a1), red4(b1)), fmaxf(red4(c1), red4(d1)));
#pragma unroll
    for (int s = 16; s > 0; s >>= 1) {
        am0 = fmaxf(am0, __shfl_xor_sync(0xffffffffu, am0, s));
        am1 = fmaxf(am1, __shfl_xor_sync(0xffffffffu, am1, s));
    }
    float s20 = (am0 > 0.0f) ? (32.0f / am0) : 0.0f;
    float s21 = (am1 > 0.0f) ? (32.0f / am1) : 0.0f;

    const unsigned long long* __restrict__ lutl = lut + (lane & 15);

    // |x| <= am  =>  t in [0, 64+eps]; m = t + 2^23 has bits 0x4B000000 + bi
    // with bi in [0,64], so (bits & 127) IS the bucket index. LDS.64:
    // half-warp phase = 16 lanes x 8B = 128B, distinct bank pair per lane
    // -> conflict-free for arbitrary per-lane buckets.
    auto q = [&](float xv, float s2, float am) -> float {
        float t = fmaf(xv, s2, 32.0f);
        float m = t + 8388608.0f;
        unsigned bi = ((unsigned)__float_as_int(m)) & 127u;
        unsigned long long raw = lutl[bi * REPS];
        float bnd = __uint_as_float((unsigned)raw);
        unsigned codes = (unsigned)(raw >> 32);
        unsigned s = codes >> ((t > bnd) ? 16 : 0);   // pick hi or lo half
        float v = __half2float(__ushort_as_half((unsigned short)s));
        return v * am;                                 // NF4[idx] (fp16) * absmax
    };

    // ---- block 0 ----
    a0.x = q(a0.x, s20, am0); a0.y = q(a0.y, s20, am0); a0.z = q(a0.z, s20, am0); a0.w = q(a0.w, s20, am0);
    b0.x = q(b0.x, s20, am0); b0.y = q(b0.y, s20, am0); b0.z = q(b0.z, s20, am0); b0.w = q(b0.w, s20, am0);
    c0.x = q(c0.x, s20, am0); c0.y = q(c0.y, s20, am0); c0.z = q(c0.z, s20, am0); c0.w = q(c0.w, s20, am0);
    d0.x = q(d0.x, s20, am0); d0.y = q(d0.y, s20, am0); d0.z = q(d0.z, s20, am0); d0.w = q(d0.w, s20, am0);
    __stcs(xo0 + 0,  a0);
    __stcs(xo0 + 32, b0);
    __stcs(xo0 + 64, c0);
    __stcs(xo0 + 96, d0);

    // ---- block 1 (data resident since the batched loads) ----
    if (has1) {
        a1.x = q(a1.x, s21, am1); a1.y = q(a1.y, s21, am1); a1.z = q(a1.z, s21, am1); a1.w = q(a1.w, s21, am1);
        b1.x = q(b1.x, s21, am1); b1.y = q(b1.y, s21, am1); b1.z = q(b1.z, s21, am1); b1.w = q(b1.w, s21, am1);
        c1.x = q(c1.x, s21, am1); c1.y = q(c1.y, s21, am1); c1.z = q(c1.z, s21, am1); c1.w = q(c1.w, s21, am1);
        d1.x = q(d1.x, s21, am1); d1.y = q(d1.y, s21, am1); d1.z = q(d1.z, s21, am1); d1.w = q(d1.w, s21, am1);
        __stcs(xo1 + 0,  a1);
        __stcs(xo1 + 32, b1);
        __stcs(xo1 + 64, c1);
        __stcs(xo1 + 96, d1);
    }
}

extern "C" void kernel_launch(void* const* d_in, const int* in_sizes, int n_in,
                              void* d_out, int out_size) {
    const float* x = (const float*)d_in[0];
    float* out = (float*)d_out;
    int n = in_sizes[0];
    int nblk = n / 512;                 // reference requires n % 512 == 0
    int npair = (nblk + 1) / 2;
    int ctas = (npair + 7) / 8;         // 8 warps (= 8 block-pairs) per CTA
    nf4_qdq_kernel<<<ctas, 256>>>(x, out, nblk);
}